// round 2
// baseline (speedup 1.0000x reference)
#include <cuda_runtime.h>

#define KK 16
#define LL 64
#define BB 32768

// ROLE 0: add path (cyclic convolution Q, carry)
// ROLE 1: sub path (cyclic correlation C, borrow)
template<int ROLE>
__device__ __forceinline__ void run_role(
    const float4* __restrict__ p1, const float4* __restrict__ p2,
    float4* __restrict__ po)
{
    float st = 0.f;  // carry1 (ROLE 0) or borrow1 (ROLE 1); complement is 1-st

    // software pipeline: preload digit 0
    float4 A0 = p1[0], A1 = p1[1], A2 = p1[2], A3 = p1[3];
    float4 B0 = p2[0], B1 = p2[1], B2 = p2[2], B3 = p2[3];

    #pragma unroll 1
    for (int l = 0; l < LL; ++l) {
        float a[16] = {A0.x, A0.y, A0.z, A0.w, A1.x, A1.y, A1.z, A1.w,
                       A2.x, A2.y, A2.z, A2.w, A3.x, A3.y, A3.z, A3.w};
        float c[16] = {B0.x, B0.y, B0.z, B0.w, B1.x, B1.y, B1.z, B1.w,
                       B2.x, B2.y, B2.z, B2.w, B3.x, B3.y, B3.z, B3.w};

        // prefetch next digit
        if (l < LL - 1) {
            const int o = (l + 1) * 4;
            A0 = p1[o]; A1 = p1[o + 1]; A2 = p1[o + 2]; A3 = p1[o + 3];
            B0 = p2[o]; B1 = p2[o + 1]; B2 = p2[o + 2]; B3 = p2[o + 3];
        }

        // cyclic conv/corr: Q[v] = sum_{(i +/- j) & 15 == v} a_i * c_j
        float Q[16];
        #pragma unroll
        for (int v = 0; v < 16; ++v) Q[v] = 0.f;

        #pragma unroll
        for (int i = 0; i < 16; ++i) {
            #pragma unroll
            for (int j = 0; j < 16; ++j) {
                const int v = (ROLE == 0) ? ((i + j) & 15) : ((i - j + 16) & 15);
                Q[v] = fmaf(a[i], c[j], Q[v]);
            }
        }

        // suffix sums of c: Csuf[m] = sum_{j>=m} c_j  (m = 1..15)
        float Csuf[16];
        Csuf[15] = c[15];
        #pragma unroll
        for (int m = 14; m >= 1; --m) Csuf[m] = Csuf[m + 1] + c[m];

        // S = SH (P(i+j>=16)) for add, DL (P(i<j)) for sub
        float S = 0.f;
        if (ROLE == 0) {
            #pragma unroll
            for (int i = 1; i < 16; ++i) S = fmaf(a[i], Csuf[16 - i], S);
        } else {
            #pragma unroll
            for (int i = 0; i < 15; ++i) S = fmaf(a[i], Csuf[i + 1], S);
        }

        // outputs: res[v] = (1-st)*Q[v] + st*Q[(v + shift) & 15]
        float r[16];
        #pragma unroll
        for (int v = 0; v < 16; ++v) {
            const int w = (ROLE == 0) ? ((v + 15) & 15) : ((v + 1) & 15);
            r[v] = fmaf(st, Q[w] - Q[v], Q[v]);
        }

        // state update: st' = S + st * Q[pivot]
        const float piv = (ROLE == 0) ? Q[15] : Q[0];
        st = fmaf(st, piv, S);

        const int ob = l * 4;
        po[ob + 0] = make_float4(r[0],  r[1],  r[2],  r[3]);
        po[ob + 1] = make_float4(r[4],  r[5],  r[6],  r[7]);
        po[ob + 2] = make_float4(r[8],  r[9],  r[10], r[11]);
        po[ob + 3] = make_float4(r[12], r[13], r[14], r[15]);
    }
}

__global__ __launch_bounds__(128) void bitop_kernel(
    const float* __restrict__ op1, const float* __restrict__ op2,
    float* __restrict__ out)
{
    const int tid  = threadIdx.x;
    const int e    = blockIdx.x * 64 + (tid & 63);   // batch element
    const int role = tid >> 6;                        // 0 = add, 1 = sub

    const size_t row = (size_t)e * (LL * KK / 4);
    const float4* p1 = reinterpret_cast<const float4*>(op1) + row;
    const float4* p2 = reinterpret_cast<const float4*>(op2) + row;

    if (role == 0) {
        float4* po = reinterpret_cast<float4*>(out) + row;
        run_role<0>(p1, p2, po);
    } else {
        float4* po = reinterpret_cast<float4*>(out + (size_t)BB * LL * KK) + row;
        run_role<1>(p1, p2, po);
    }
}

extern "C" void kernel_launch(void* const* d_in, const int* in_sizes, int n_in,
                              void* d_out, int out_size)
{
    const float* op1 = (const float*)d_in[0];
    const float* op2 = (const float*)d_in[1];
    float* out = (float*)d_out;

    bitop_kernel<<<BB / 64, 128>>>(op1, op2, out);
}